// round 16
// baseline (speedup 1.0000x reference)
#include <cuda_runtime.h>
#include <cuda_bf16.h>
#include <cstdint>

#define NN 23
#define BSZ 16384
#define MTOT (BSZ * NN)          // 376832 = 2944*128
#define NT 256
#define SWZ(o) ((o) ^ (((o) >> 3) & 0x70))

// ---------------- 4 big aliased regions + 1 small region -------------------
#define REGB ((size_t)MTOT * 256 * 4)
__device__ __align__(128) char g_R0[REGB];
__device__ __align__(128) char g_R1[REGB];
__device__ __align__(128) char g_R2[REGB];
__device__ __align__(128) char g_R3[REGB];
#define RS_PLH 0
#define RS_PLL ((size_t)BSZ * 256 * 2)
#define RS_H1H ((size_t)BSZ * 256 * 4)
#define RS_H1L (RS_H1H + (size_t)BSZ * 128 * 2)
#define RS_H2  (RS_H1H + (size_t)BSZ * 128 * 4)
#define RS_PLF (RS_H2 + (size_t)BSZ * 64 * 4)
#define RS_SUMF (RS_PLF + (size_t)BSZ * 256 * 4)
#define RS_SPH  (RS_SUMF + (size_t)BSZ * 256 * 4)
#define RS_SPL  (RS_SPH + (size_t)BSZ * 256 * 2)
#define RS_CN   (RS_SPL + (size_t)BSZ * 256 * 2)
#define RS_SZ   (RS_CN + (size_t)BSZ * 768 * 4)
__device__ __align__(128) char g_RS[RS_SZ];

// ---------------- weight arena (pre-swizzled chunk images), elem offsets
#define W1OFF 0
#define W2OFF 8192
#define FQOFF 40960              // fused folded QKV (NEGATED): O=768, nch=4
#define WQOFF 237568
#define WKOFF 303104
#define WVOFF 368640
#define OWOFF 434176
#define O1OFF 499712
#define O2OFF 532480
#define WSZ   540672
__device__ __align__(16) __nv_bfloat16 g_Wh[WSZ];
__device__ __align__(16) __nv_bfloat16 g_Wl[WSZ];

// bias arena (f32); [ZBO, ZBO+768) never written -> zeros
#define B1O 0
#define B2O 128
#define BQO 1408
#define BKO 1664
#define BVO 1920
#define OBO 2176
#define OB1O 2432
#define OB2O 2560
#define W3HO 2624
#define B3HO 2752
#define FQB 3072
#define ZBO 3968
__device__ float g_Ba[5120];

// ---------------- helpers
__device__ __forceinline__ unsigned smem_u32(const void* p) {
    return (unsigned)__cvta_generic_to_shared(p);
}
__device__ __forceinline__ void ldm4(uint32_t* r, unsigned a) {
    asm volatile("ldmatrix.sync.aligned.m8n8.x4.shared.b16 {%0,%1,%2,%3}, [%4];"
                 : "=r"(r[0]), "=r"(r[1]), "=r"(r[2]), "=r"(r[3]) : "r"(a));
}
__device__ __forceinline__ void mma16816(float* c, const uint32_t* a,
                                         const uint32_t* b) {
    asm volatile(
        "mma.sync.aligned.m16n8k16.row.col.f32.bf16.bf16.f32 "
        "{%0,%1,%2,%3},{%4,%5,%6,%7},{%8,%9},{%0,%1,%2,%3};"
        : "+f"(c[0]), "+f"(c[1]), "+f"(c[2]), "+f"(c[3])
        : "r"(a[0]), "r"(a[1]), "r"(a[2]), "r"(a[3]), "r"(b[0]), "r"(b[1]));
}
__device__ __forceinline__ void split2(float a, float b,
                                       __nv_bfloat162& h2, __nv_bfloat162& l2) {
    __nv_bfloat16 ah = __float2bfloat16(a), bh = __float2bfloat16(b);
    h2 = __halves2bfloat162(ah, bh);
    l2 = __halves2bfloat162(__float2bfloat16(a - __bfloat162float(ah)),
                            __float2bfloat16(b - __bfloat162float(bh)));
}
__device__ __forceinline__ void bulk_cp(unsigned d, const void* s,
                                        unsigned bytes, unsigned mbar) {
    asm volatile(
        "cp.async.bulk.shared::cluster.global.mbarrier::complete_tx::bytes "
        "[%0], [%1], %2, [%3];"
        :: "r"(d), "l"(s), "r"(bytes), "r"(mbar) : "memory");
}
__device__ __forceinline__ void mbar_wait(unsigned m, int par) {
    uint32_t done;
    asm volatile("{\n\t.reg .pred p;\n\t"
                 "mbarrier.try_wait.parity.acquire.cta.shared::cta.b64 p, [%1], %2;\n\t"
                 "selp.b32 %0,1,0,p;\n\t}"
                 : "=r"(done) : "r"(m), "r"((uint32_t)par) : "memory");
    if (!done)
        asm volatile("{\n\t.reg .pred P1;\n\tWL_%=:\n\t"
                     "mbarrier.try_wait.parity.acquire.cta.shared::cta.b64 P1, [%0], %1, 0x989680;\n\t"
                     "@P1 bra.uni WD_%=;\n\tbra.uni WL_%=;\n\tWD_%=:\n\t}"
                     :: "r"(m), "r"((uint32_t)par) : "memory");
}

// ---------------- fold kernels: F_g = w_g @ W3 ; fb = b_g + 22*w_g@b3 ------
__global__ void fold_k(const float* __restrict__ qw, const float* __restrict__ kw,
                       const float* __restrict__ vw, const float* __restrict__ w3,
                       float* __restrict__ scr) {
    int r = blockIdx.x, g = blockIdx.y, t = threadIdx.x;
    __shared__ float row[256];
    const float* w = g == 0 ? qw : (g == 1 ? kw : vw);
    row[t] = w[r * 256 + t];
    __syncthreads();
    float a = 0.f;
#pragma unroll 8
    for (int j = 0; j < 256; j++) a += row[j] * w3[j * 256 + t];
    scr[((size_t)(g * 256 + r)) * 256 + t] = a;
}
__global__ void fold_b(const float* qw, const float* kw, const float* vw,
                       const float* qb, const float* kb, const float* vb,
                       const float* b3) {
    int o = blockIdx.x * 256 + threadIdx.x;
    int g = o >> 8, r = o & 255;
    const float* w = g == 0 ? qw : (g == 1 ? kw : vw);
    const float* b = g == 0 ? qb : (g == 1 ? kb : vb);
    float a = 0.f;
#pragma unroll 8
    for (int j = 0; j < 256; j++) a += w[r * 256 + j] * b3[j];
    g_Ba[FQB + o] = b[r] + 22.f * a;
}

// ---------------- merged weight prep: 9 segments in one launch -------------
struct PrepAll {
    const float* src[9];
    int O[9], K[9], nch[9];
    float scale[9];
    int off[9];
};
__global__ void prep_w_all(PrepAll pa) {
    int seg = blockIdx.y;
    const float* __restrict__ src = pa.src[seg];
    int O = pa.O[seg], K = pa.K[seg], nch = pa.nch[seg], off = pa.off[seg];
    float scale = pa.scale[seg];
    int tot = nch * O * 64;
    for (int e = blockIdx.x * blockDim.x + threadIdx.x; e < tot;
         e += gridDim.x * blockDim.x) {
        int kc = e / (O * 64), rem = e - kc * O * 64;
        int r = rem >> 6, kk = rem & 63, k = kc * 64 + kk;
        float v = (k < K) ? src[(size_t)r * K + k] * scale : 0.f;
        __nv_bfloat16 h = __float2bfloat16(v);
        int dst = off + kc * O * 64 + (SWZ(r * 128 + kk * 2) >> 1);
        g_Wh[dst] = h;
        g_Wl[dst] = __float2bfloat16(v - __bfloat162float(h));
    }
}
__global__ void prep_x(const float* __restrict__ x,
                       __nv_bfloat16* __restrict__ XAh,
                       __nv_bfloat16* __restrict__ XAl) {
    for (size_t e = (size_t)blockIdx.x * blockDim.x + threadIdx.x;
         e < (size_t)MTOT * 64; e += (size_t)gridDim.x * blockDim.x) {
        size_t m = e >> 6;
        int c = (int)(e & 63);
        float v = (c < 7) ? x[m * 7 + c] : 0.f;
        size_t tile = m >> 7;
        int rt = (int)(m & 127);
        size_t dst = tile * 8192 + (SWZ(rt * 128 + c * 2) >> 1);
        __nv_bfloat16 h = __float2bfloat16(v);
        XAh[dst] = h;
        XAl[dst] = __float2bfloat16(v - __bfloat162float(h));
    }
}
__global__ void prep_bias(const float* b1, const float* b2,
                          const float* inb, const float* ob, const float* ob1,
                          const float* ob2, const float* ow3, const float* ob3) {
    const float s = 0.17677669529663687f;
    int t = threadIdx.x;
    for (int i = t; i < 128; i += 256) g_Ba[B1O + i] = b1[i];
    for (int i = t; i < 256; i += 256) g_Ba[B2O + i] = b2[i];
    for (int i = t; i < 256; i += 256) g_Ba[BQO + i] = inb[i] * s;
    for (int i = t; i < 256; i += 256) g_Ba[BKO + i] = inb[256 + i];
    for (int i = t; i < 256; i += 256) g_Ba[BVO + i] = inb[512 + i];
    for (int i = t; i < 256; i += 256) g_Ba[OBO + i] = ob[i];
    for (int i = t; i < 128; i += 256) g_Ba[OB1O + i] = ob1[i];
    for (int i = t; i < 64;  i += 256) g_Ba[OB2O + i] = ob2[i];
    for (int i = t; i < 128; i += 256) g_Ba[W3HO + i] = ow3[i];
    for (int i = t; i < 2;   i += 256) g_Ba[B3HO + i] = ob3[i];
}
__global__ void init_misc(float* __restrict__ SUMF, float* __restrict__ PLF) {
    for (size_t i = (size_t)blockIdx.x * blockDim.x + threadIdx.x;
         i < (size_t)BSZ * 256; i += (size_t)gridDim.x * blockDim.x) {
        SUMF[i] = 0.f;
        reinterpret_cast<unsigned*>(PLF)[i] = 0xff800000u;  // -inf
    }
}
__global__ __launch_bounds__(128) void vec2pair(const float* __restrict__ V,
                                                __nv_bfloat16* __restrict__ Ph,
                                                __nv_bfloat16* __restrict__ Pl) {
    int b = blockIdx.x, p = threadIdx.x;
    float2 t = *reinterpret_cast<const float2*>(V + (size_t)b * 256 + 2 * p);
    size_t tile = b >> 7; int rt = b & 127;
    size_t e = (tile * 4 + (p >> 5)) * 8192 + (SWZ(rt * 128 + ((2 * p) & 63) * 2) >> 1);
    __nv_bfloat162 h2, l2;
    split2(t.x, t.y, h2, l2);
    *reinterpret_cast<__nv_bfloat162*>(Ph + e) = h2;
    *reinterpret_cast<__nv_bfloat162*>(Pl + e) = l2;
}

// ---------------------------------------------------------------------------
// HMMA GEMM: CTA tile M=128 x 64, K = nch*64, 3-term bf16 split, occ 2,
// 2-stage cp.async.bulk ring.
// outmode: 0 = bf16 pair image, 1 = f32 plane, 2 = fused maxpool (atomics).
// Cb (optional): per-(batch,col) extra bias, added as csign*Cb[b*768+cg].
// ---------------------------------------------------------------------------
#define BUFB 49152
#define GSMEM (1024 + 2 * BUFB + 64)
__global__ void __launch_bounds__(NT, 2) gemm_hmma(
    const __nv_bfloat16* __restrict__ Ah_, const __nv_bfloat16* __restrict__ Al_,
    const __nv_bfloat16* __restrict__ Ah1_, const __nv_bfloat16* __restrict__ Al1_,
    const __nv_bfloat16* __restrict__ Ah2_, const __nv_bfloat16* __restrict__ Al2_,
    int nch, int woff, int wzs, int Nfull, int boff, int act, int outmode,
    __nv_bfloat16* __restrict__ Oh, __nv_bfloat16* __restrict__ Ol,
    __nv_bfloat16* __restrict__ Oh1, __nv_bfloat16* __restrict__ Ol1,
    __nv_bfloat16* __restrict__ Oh2, __nv_bfloat16* __restrict__ Ol2,
    float* __restrict__ Of, float* __restrict__ Of1, float* __restrict__ Of2,
    const float* __restrict__ Cb, float csign) {
    extern __shared__ char smem[];
    const unsigned sb = (smem_u32(smem) + 1023u) & ~1023u;
    char* scm = smem + (sb - smem_u32(smem));
    const unsigned mb0 = sb + 2 * BUFB, mb1 = mb0 + 8;
    const int tid = threadIdx.x, w = tid >> 5, l = tid & 31;
    const int m0 = (w >> 1) * 32, n0l = (w & 1) * 32;
    const int n0g = blockIdx.x * 64;
    const int mt = blockIdx.y;
    const int z = blockIdx.z;
    const __nv_bfloat16* Ahp = z == 0 ? Ah_ : (z == 1 ? Ah1_ : Ah2_);
    const __nv_bfloat16* Alp = z == 0 ? Al_ : (z == 1 ? Al1_ : Al2_);
    float* Ofz = z == 0 ? Of : (z == 1 ? Of1 : Of2);
    const int woz = woff + z * wzs, boz = boff + z * 256;

    float acc[2][4][4];
#pragma unroll
    for (int mi = 0; mi < 2; mi++)
#pragma unroll
        for (int nj = 0; nj < 4; nj++)
#pragma unroll
            for (int q = 0; q < 4; q++) acc[mi][nj][q] = 0.f;

    if (tid == 0) {
        asm volatile("mbarrier.init.shared.b64 [%0], 1;" :: "r"(mb0) : "memory");
        asm volatile("mbarrier.init.shared.b64 [%0], 1;" :: "r"(mb1) : "memory");
    }
    __syncthreads();

    auto stage = [&](int c) {
        if (tid == 0) {
            size_t ao = ((size_t)mt * nch + c) * 16384;
            size_t bo = ((size_t)woz + (size_t)c * Nfull * 64 +
                         (size_t)n0g * 64) * 2;
            unsigned d = sb + (unsigned)(c & 1) * BUFB;
            unsigned mb = (c & 1) ? mb1 : mb0;
            asm volatile("mbarrier.arrive.expect_tx.shared.b64 _, [%0], %1;"
                         :: "r"(mb), "r"(49152u) : "memory");
            bulk_cp(d, (const char*)Ahp + ao, 16384, mb);
            bulk_cp(d + 16384, (const char*)Alp + ao, 16384, mb);
            bulk_cp(d + 32768, (const char*)g_Wh + bo, 8192, mb);
            bulk_cp(d + 40960, (const char*)g_Wl + bo, 8192, mb);
        }
    };

    stage(0);
    if (nch > 1) stage(1);

    const int rowA = l & 15, kA = (l >> 4) * 8;
    const int nB = (l & 7) + ((l >> 4) & 1) * 8, kB = ((l >> 3) & 1) * 8;
    const unsigned offA0 = SWZ((m0 + rowA) * 128 + kA * 2);
    const unsigned offA1 = SWZ((m0 + 16 + rowA) * 128 + kA * 2);
    const unsigned offB0 = SWZ((n0l + nB) * 128 + kB * 2);
    const unsigned offB1 = SWZ((n0l + 16 + nB) * 128 + kB * 2);

    int par0 = 0, par1 = 0;
    for (int c = 0; c < nch; c++) {
        if ((c & 1) == 0) { mbar_wait(mb0, par0); par0 ^= 1; }
        else              { mbar_wait(mb1, par1); par1 ^= 1; }

        const unsigned bb = sb + (unsigned)(c & 1) * BUFB;
        const unsigned aH0 = bb + offA0, aH1 = bb + offA1;
        const unsigned aL0 = aH0 + 16384, aL1 = aH1 + 16384;
        const unsigned bH0 = bb + 32768 + offB0, bH1 = bb + 32768 + offB1;
        const unsigned bL0 = bH0 + 8192, bL1 = bH1 + 8192;

#pragma unroll
        for (int ks = 0; ks < 4; ks++) {
            const unsigned kx = (unsigned)(ks << 5);
            uint32_t ah[2][4], al[2][4];
            ldm4(ah[0], aH0 ^ kx);
            ldm4(al[0], aL0 ^ kx);
            ldm4(ah[1], aH1 ^ kx);
            ldm4(al[1], aL1 ^ kx);
#pragma unroll
            for (int g = 0; g < 2; g++) {
                uint32_t rh[4], rl[4];
                ldm4(rh, (g ? bH1 : bH0) ^ kx);
                ldm4(rl, (g ? bL1 : bL0) ^ kx);
#pragma unroll
                for (int mi = 0; mi < 2; mi++) {
                    mma16816(acc[mi][2 * g], ah[mi], rh);
                    mma16816(acc[mi][2 * g], al[mi], rh);
                    mma16816(acc[mi][2 * g], ah[mi], rl);
                    mma16816(acc[mi][2 * g + 1], ah[mi], rh + 2);
                    mma16816(acc[mi][2 * g + 1], al[mi], rh + 2);
                    mma16816(acc[mi][2 * g + 1], ah[mi], rl + 2);
                }
            }
        }
        __syncthreads();
        if (c + 2 < nch) stage(c + 2);
    }

    // ---- epilogue ----
    const int rq = l >> 2, cq = (l & 3) * 2;
    if (outmode == 0) {
#pragma unroll
        for (int mi = 0; mi < 2; mi++)
#pragma unroll
            for (int nj = 0; nj < 4; nj++) {
                int lc = n0l + nj * 8 + cq;
                int cg = n0g + lc;
                int r0 = m0 + mi * 16 + rq, r1 = r0 + 8;
                float b0 = g_Ba[boz + cg], b1 = g_Ba[boz + cg + 1];
                float c00 = 0.f, c01 = 0.f, c10 = 0.f, c11 = 0.f;
                if (Cb) {
                    int bb0 = (mt * 128 + r0) / NN, bb1 = (mt * 128 + r1) / NN;
                    c00 = csign * Cb[(size_t)bb0 * 768 + cg];
                    c01 = csign * Cb[(size_t)bb0 * 768 + cg + 1];
                    c10 = csign * Cb[(size_t)bb1 * 768 + cg];
                    c11 = csign * Cb[(size_t)bb1 * 768 + cg + 1];
                }
                float v[4] = {acc[mi][nj][0] + b0 + c00, acc[mi][nj][1] + b1 + c01,
                              acc[mi][nj][2] + b0 + c10, acc[mi][nj][3] + b1 + c11};
                if (act) {
#pragma unroll
                    for (int q = 0; q < 4; q++)
                        v[q] = v[q] >= 0.f ? v[q] : 0.2f * v[q];
                }
                int e0 = SWZ(r0 * 128 + lc * 2), e1 = SWZ(r1 * 128 + lc * 2);
                __nv_bfloat162 h2, l2;
                split2(v[0], v[1], h2, l2);
                *reinterpret_cast<__nv_bfloat162*>(scm + e0) = h2;
                *reinterpret_cast<__nv_bfloat162*>(scm + 16384 + e0) = l2;
                split2(v[2], v[3], h2, l2);
                *reinterpret_cast<__nv_bfloat162*>(scm + e1) = h2;
                *reinterpret_cast<__nv_bfloat162*>(scm + 16384 + e1) = l2;
            }
        __syncthreads();
        int grp = n0g >> 8, lc0 = n0g & 255;
        __nv_bfloat16* OH = grp == 0 ? Oh : (grp == 1 ? Oh1 : Oh2);
        __nv_bfloat16* OL = grp == 0 ? Ol : (grp == 1 ? Ol1 : Ol2);
        const int nchO = (Nfull >= 256 ? 4 : (Nfull >> 6));
        size_t baseB = (((size_t)mt * nchO + (lc0 >> 6)) * 8192) * 2;
        char* dH = (char*)OH + baseB;
        char* dL = (char*)OL + baseB;
        for (int i = tid * 16; i < 16384; i += NT * 16) {
            *reinterpret_cast<float4*>(dH + i) =
                *reinterpret_cast<const float4*>(scm + i);
            *reinterpret_cast<float4*>(dL + i) =
                *reinterpret_cast<const float4*>(scm + 16384 + i);
        }
    } else {
        float* st = (float*)scm;  // row stride 68 floats
#pragma unroll
        for (int mi = 0; mi < 2; mi++)
#pragma unroll
            for (int nj = 0; nj < 4; nj++) {
                int lc = n0l + nj * 8 + cq;
                int cg = n0g + lc;
                float b0 = g_Ba[boz + cg], b1 = g_Ba[boz + cg + 1];
                float v[4] = {acc[mi][nj][0] + b0, acc[mi][nj][1] + b1,
                              acc[mi][nj][2] + b0, acc[mi][nj][3] + b1};
                if (act) {
#pragma unroll
                    for (int q = 0; q < 4; q++)
                        v[q] = v[q] >= 0.f ? v[q] : 0.2f * v[q];
                }
                int r0 = m0 + mi * 16 + rq, r1 = r0 + 8;
                st[r0 * 68 + lc] = v[0];
                st[r0 * 68 + lc + 1] = v[1];
                st[r1 * 68 + lc] = v[2];
                st[r1 * 68 + lc + 1] = v[3];
            }
        __syncthreads();
        if (outmode == 1) {
            size_t m0r = (size_t)mt * 128;
            for (int idx = tid; idx < 2048; idx += NT) {
                int row = idx >> 4, qq = idx & 15;
                float4 vv = *reinterpret_cast<const float4*>(st + row * 68 + qq * 4);
                *reinterpret_cast<float4*>(Ofz + (m0r + row) * Nfull + n0g + qq * 4) = vv;
            }
        } else {  // outmode == 2: fused maxpool
            const int mr0 = mt * 128;
            const int bfirst = mr0 / NN;
            const int blast = (mr0 + 127) / NN;
            const int nb = blast - bfirst + 1;
            for (int idx = tid; idx < nb * 64; idx += NT) {
                int bl = idx >> 6, col = idx & 63;
                int b = bfirst + bl;
                int rlo = b * NN, rhi = rlo + NN;
                if (rlo < mr0) rlo = mr0;
                if (rhi > mr0 + 128) rhi = mr0 + 128;
                float mx = -1e30f;
                for (int r = rlo; r < rhi; r++)
                    mx = fmaxf(mx, st[(r - mr0) * 68 + col]);
                float* p = Ofz + (size_t)b * 256 + n0g + col;
                if (mx >= 0.f)
                    atomicMax(reinterpret_cast<int*>(p), __float_as_int(mx));
                else
                    atomicMin(reinterpret_cast<unsigned*>(p), __float_as_uint(mx));
            }
        }
    }
}

// ---------------------------------------------------------------------------
// FUSED layer1+layer2 + per-batch colsum atomics
// ---------------------------------------------------------------------------
#define F_SMEM (1024 + 65536 + 32768 + 64)
__global__ void __launch_bounds__(NT, 2) gemm12_k(
    const __nv_bfloat16* __restrict__ XAh, const __nv_bfloat16* __restrict__ XAl,
    __nv_bfloat16* __restrict__ Oh, __nv_bfloat16* __restrict__ Ol,
    float* __restrict__ SUMF) {
    extern __shared__ char smem[];
    const unsigned sb = (smem_u32(smem) + 1023u) & ~1023u;
    char* scm = smem + (sb - smem_u32(smem));
    const unsigned R0 = sb, R1 = sb + 65536;
    const unsigned mb0 = sb + 98304, mb1 = mb0 + 8;
    const int tid = threadIdx.x, w = tid >> 5, l = tid & 31;
    const int m0 = (w >> 1) * 32, n0l = (w & 1) * 64;
    const int n0g = blockIdx.x * 128;
    const int mt = blockIdx.y;

    if (tid == 0) {
        asm volatile("mbarrier.init.shared.b64 [%0], 1;" :: "r"(mb0) : "memory");
        asm volatile("mbarrier.init.shared.b64 [%0], 1;" :: "r"(mb1) : "memory");
    }
    __syncthreads();

    if (tid == 0) {
        size_t ao = (size_t)mt * 16384;
        asm volatile("mbarrier.arrive.expect_tx.shared.b64 _, [%0], %1;"
                     :: "r"(mb0), "r"(65536u) : "memory");
        bulk_cp(R0, (const char*)XAh + ao, 16384, mb0);
        bulk_cp(R0 + 16384, (const char*)XAl + ao, 16384, mb0);
        bulk_cp(R0 + 32768, (const char*)g_Wh + (size_t)W1OFF * 2, 16384, mb0);
        bulk_cp(R0 + 49152, (const char*)g_Wl + (size_t)W1OFF * 2, 16384, mb0);
        size_t bo = ((size_t)W2OFF + (size_t)n0g * 64) * 2;
        asm volatile("mbarrier.arrive.expect_tx.shared.b64 _, [%0], %1;"
                     :: "r"(mb1), "r"(32768u) : "memory");
        bulk_cp(R1, (const char*)g_Wh + bo, 16384, mb1);
        bulk_cp(R1 + 16384, (const char*)g_Wl + bo, 16384, mb1);
    }

    const int rowA = l & 15, kA = (l >> 4) * 8;
    const int nB = (l & 7) + ((l >> 4) & 1) * 8, kB = ((l >> 3) & 1) * 8;
    const unsigned offA0 = SWZ((m0 + rowA) * 128 + kA * 2);
    const unsigned offA1 = SWZ((m0 + 16 + rowA) * 128 + kA * 2);
    unsigned offB[4];
#pragma unroll
    for (int g = 0; g < 4; g++)
        offB[g] = SWZ((n0l + g * 16 + nB) * 128 + kB * 2);

    float acc[2][8][4];
#pragma unroll
    for (int mi = 0; mi < 2; mi++)
#pragma unroll
        for (int nj = 0; nj < 8; nj++)
#pragma unroll
            for (int q = 0; q < 4; q++) acc[mi][nj][q] = 0.f;

    // ---- phase 1 ----
    mbar_wait(mb0, 0);
    {
        const unsigned aH0 = R0 + offA0, aH1 = R0 + offA1;
        const unsigned aL0 = aH0 + 16384, aL1 = aH1 + 16384;
#pragma unroll
        for (int ks = 0; ks < 4; ks++) {
            const unsigned kx = (unsigned)(ks << 5);
            uint32_t ah[2][4], al[2][4];
            ldm4(ah[0], aH0 ^ kx);
            ldm4(al[0], aL0 ^ kx);
            ldm4(ah[1], aH1 ^ kx);
            ldm4(al[1], aL1 ^ kx);
#pragma unroll
            for (int g = 0; g < 4; g++) {
                const unsigned bH = R0 + 32768 + offB[g];
                const unsigned bL = bH + 16384;
                uint32_t rh[4], rl[4];
                ldm4(rh, bH ^ kx);
                ldm4(rl, bL ^ kx);
#pragma unroll
                for (int mi = 0; mi < 2; mi++) {
                    mma16816(acc[mi][2 * g], ah[mi], rh);
                    mma16816(acc[mi][2 * g], al[mi], rh);
                    mma16816(acc[mi][2 * g], ah[mi], rl);
                    mma16816(acc[mi][2 * g + 1], ah[mi], rh + 2);
                    mma16816(acc[mi][2 * g + 1], al[mi], rh + 2);
                    mma16816(acc[mi][2 * g + 1], ah[mi], rl + 2);
                }
            }
        }
    }
    __syncthreads();

    // ---- write S1 image into R0 ----
    const int rq = l >> 2, cq = (l & 3) * 2;
#pragma unroll
    for (int mi = 0; mi < 2; mi++)
#pragma unroll
        for (int nj = 0; nj < 8; nj++) {
            int lc = n0l + nj * 8 + cq;
            float b0 = g_Ba[B1O + lc], b1 = g_Ba[B1O + lc + 1];
            float v[4] = {acc[mi][nj][0] + b0, acc[mi][nj][1] + b1,
                          acc[mi][nj][2] + b0, acc[mi][nj][3] + b1};
#pragma unroll
            for (int q = 0; q < 4; q++) v[q] = v[q] >= 0.f ? v[q] : 0.2f * v[q];
            int r0 = m0 + mi * 16 + rq, r1 = r0 + 8;
            int ch = lc >> 6, cc = lc & 63;
            unsigned e0 = (unsigned)ch * 16384 + SWZ(r0 * 128 + cc * 2);
            unsigned e1 = (unsigned)ch * 16384 + SWZ(r1 * 128 + cc * 2);
            __nv_bfloat162 h2, l2;
            split2(v[0], v[1], h2, l2);
            *reinterpret_cast<__nv_bfloat162*>(scm + e0) = h2;
            *reinterpret_cast<__nv_bfloat162*>(scm + e0 + 32768) = l2;
            split2(v[2], v[3], h2, l2);
            *reinterpret_cast<__nv_bfloat162*>(scm + e1) = h2;
            *reinterpret_cast<__nv_bfloat162*>(scm + e1 + 32768) = l2;
        }
    __syncthreads();

    // ---- phase 2 ----
#pragma unroll
    for (int mi = 0; mi < 2; mi++)
#pragma unroll
        for (int nj = 0; nj < 8; nj++)
#pragma unroll
            for (int q = 0; q < 4; q++) acc[mi][nj][q] = 0.f;

    int par1 = 0;
    for (int c = 0; c < 2; c++) {
        mbar_wait(mb1, par1);
        par1 ^= 1;
        const unsigned aH0 = R0 + c * 16384 + offA0;
        const unsigned aH1 = R0 + c * 16384 + offA1;
        const unsigned aL0 = aH0 + 32768, aL1 = aH1 + 32768;
#pragma unroll
        for (int ks = 0; ks < 4; ks++) {
            const unsigned kx = (unsigned)(ks << 5);
            uint32_t ah[2][4], al[2][4];
            ldm4(ah[0], aH0 ^ kx);
            ldm4(al[0], aL0 ^ kx);
            ldm4(ah[1], aH1 ^ kx);
            ldm4(al[1], aL1 ^ kx);
#pragma unroll
            for (int g = 0; g < 4; g++) {
                const unsigned bH = R1 + offB[g];
                const unsigned bL = bH + 16384;
                uint32_t rh[4], rl[4];
                ldm4(rh, bH ^ kx);
                ldm4(rl, bL ^ kx);
#pragma unroll
                for (int mi = 0; mi < 2; mi++) {
                    mma16816(acc[mi][2 * g], ah[mi], rh);
                    mma16816(acc[mi][2 * g], al[mi], rh);
                    mma16816(acc[mi][2 * g], ah[mi], rl);
                    mma16816(acc[mi][2 * g + 1], ah[mi], rh + 2);
                    mma16816(acc[mi][2 * g + 1], al[mi], rh + 2);
                    mma16816(acc[mi][2 * g + 1], ah[mi], rl + 2);
                }
            }
        }
        __syncthreads();
        if (c == 0 && tid == 0) {
            size_t bo = ((size_t)W2OFF + (size_t)256 * 64 + (size_t)n0g * 64) * 2;
            asm volatile("mbarrier.arrive.expect_tx.shared.b64 _, [%0], %1;"
                         :: "r"(mb1), "r"(32768u) : "memory");
            bulk_cp(R1, (const char*)g_Wh + bo, 16384, mb1);
            bulk_cp(R1 + 16384, (const char*)g_Wl + bo, 16384, mb1);
        }
    }

    // ---- epilogue: stage S2 slice + store + colsum atomics ----
#pragma unroll
    for (int mi = 0; mi < 2; mi++)
#pragma unroll
        for (int nj = 0; nj < 8; nj++) {
            int lc = n0l + nj * 8 + cq;
            int cg = n0g + lc;
            float b0 = g_Ba[B2O + cg], b1 = g_Ba[B2O + cg + 1];
            float v[4] = {acc[mi][nj][0] + b0, acc[mi][nj][1] + b1,
                          acc[mi][nj][2] + b0, acc[mi][nj][3] + b1};
#pragma unroll
            for (int q = 0; q < 4; q++) v[q] = v[q] >= 0.f ? v[q] : 0.2f * v[q];
            int r0 = m0 + mi * 16 + rq, r1 = r0 + 8;
            int ch = lc >> 6, cc = lc & 63;
            unsigned base = (unsigned)ch * 32768;
            unsigned e0 = base + SWZ(r0 * 128 + cc * 2);
            unsigned e1 = base + SWZ(r1 * 128 + cc * 2);
            __nv_bfloat162 h2, l2;
            split2(v[0], v[1], h2, l2);
            *reinterpret_cast<__nv_bfloat162*>(scm + e0) = h2;
            *reinterpret_cast<__nv_bfloat162*>(scm + e0 + 16384) = l2;
            split2(v[2], v[3], h2, l2);
            *reinterpret_cast<__nv_bfloat162*>(scm + e1) = h2;
            *reinterpret_cast<__nv_bfloat162*>(scm + e1 + 16384) = l2;
        }
    __syncthreads();
    for (int ch = 0; ch < 2; ch++) {
        size_t baseB = (((size_t)mt * 4 + (n0g >> 6) + ch) * 8192) * 2;
        char* dH = (char*)Oh + baseB;
        char* dL = (char*)Ol + baseB;
        const char* sB = scm + ch * 32768;
        for (int i = tid * 16; i < 16384; i += NT * 16) {
            *reinterpret_cast<float4*>(dH + i) =
                *reinterpret_cast<const float4*>(sB + i);
            *reinterpret_cast<float4*>(dL + i) =
                *reinterpret_cast<const float4*>(sB + 16384 + i);
        }
    }
    // colsum atomics from the staged image
    {
        const int mr0 = mt * 128;
        const int bfirst = mr0 / NN;
        const int blast = (mr0 + 127) / NN;
        const int nb = blast - bfirst + 1;
        for (int idx = tid; idx < nb * 128; idx += NT) {
            int bl = idx >> 7, col = idx & 127;
            int b = bfirst + bl;
            int rlo = b * NN, rhi = rlo + NN;
            if (rlo < mr0) rlo = mr0;
            if (rhi > mr0 + 128) rhi = mr0 + 128;
            if (rlo >= rhi) continue;
            int ch = col >> 6, cc = col & 63;
            float s = 0.f;
            for (int r = rlo; r < rhi; r++) {
                unsigned e = (unsigned)ch * 32768 + SWZ((r - mr0) * 128 + cc * 2);
                float hi = __bfloat162float(
                    *reinterpret_cast<__nv_bfloat16*>(scm + e));
                float lo = __bfloat162float(
                    *reinterpret_cast<__nv_bfloat16*>(scm + e + 16384));
                s += hi + lo;
            }
            atomicAdd(&SUMF[(size_t)b * 256 + n0g + col], s);
        }
    }
}

// ---------------- attention per batch (fp32), ctx -> swz bf16 pair
#define ATT_FLOATS (5888 + 6144 + 5888 + 4416)
__global__ __launch_bounds__(NT) void att_k(const float* __restrict__ QH,
                                            const float* __restrict__ KH,
                                            const float* __restrict__ VH,
                                            __nv_bfloat16* __restrict__ CXh,
                                            __nv_bfloat16* __restrict__ CXl) {
    extern __shared__ float sm[];
    float* q = sm;
    float* kT = q + 5888;
    float* v = kT + 6144;
    float* S = v + 5888;
    const int tid = threadIdx.x, b = blockIdx.x;
    const size_t base = (size_t)b * NN * 256;

    for (int i = tid; i < 1472; i += NT) {
        reinterpret_cast<float4*>(q)[i] = reinterpret_cast<const float4*>(QH + base)[i];
        reinterpret_cast<float4*>(v)[i] = reinterpret_cast<const float4*>(VH + base)[i];
    }
    for (int i = tid; i < 5888; i += NT) {
        int m = i >> 8, c = i & 255;
        kT[c * 24 + m] = KH[base + (size_t)m * 256 + c];
    }
    __syncthreads();

    int w = tid >> 5, lane = tid & 31;
    for (int task = w; task < 184; task += 8) {
        int h = task / 23, n = task - h * 23;
        const float* qr = q + n * 256 + h * 32;
        float a = 0.f;
        if (lane < NN) {
#pragma unroll
            for (int d = 0; d < 32; d++) a += qr[d] * kT[(h * 32 + d) * 24 + lane];
        }
        float mx = (lane < NN) ? a : -1e30f;
#pragma unroll
        for (int o = 16; o; o >>= 1) mx = fmaxf(mx, __shfl_xor_sync(~0u, mx, o));
        float e = (lane < NN) ? __expf(a - mx) : 0.f;
        float s = e;
#pragma unroll
        for (int o = 16; o; o >>= 1) s += __shfl_xor_sync(~0u, s, o);
        if (lane < NN) S[h * 552 + n * 24 + lane] = e / s;
    }
    __syncthreads();

    for (int idx = tid; idx < NN * 128; idx += NT) {
        int n = idx >> 7, p = idx & 127, h = p >> 4;
        const float* Sr = S + h * 552 + n * 24;
        const float* vc = v + 2 * p;
        float ax = 0.f, ay = 0.f;
#pragma unroll
        for (int m = 0; m < NN; m++) {
            float s = Sr[m];
            ax += s * vc[m * 256];
            ay += s * vc[m * 256 + 1];
        }
        size_t mr = (size_t)b * NN + n;
        size_t tile = mr >> 7; int rt = (int)(mr & 127);
        size_t e = (tile * 4 + (p >> 5)) * 8192 + (SWZ(rt * 128 + ((2 * p) & 63) * 2) >> 1);
        __nv_bfloat162 h2, l2;
        split2(ax, ay, h2, l2);
        *reinterpret_cast<__nv_bfloat162*>(CXh + e) = h2;
        *reinterpret_cast<__nv_bfloat162*>(CXl + e) = l2;
    }
}

// ---------------- pool image + head3
__global__ __launch_bounds__(128) void pool2pair(const float* __restrict__ PLF,
                                                 __nv_bfloat16* __restrict__ PLh,
                                                 __nv_bfloat16* __restrict__ PLl) {
    int b = blockIdx.x, p = threadIdx.x;
    float2 t = *reinterpret_cast<const float2*>(PLF + (size_t)b * 256 + 2 * p);
    size_t tile = b >> 7; int rt = b & 127;
    size_t e = (tile * 4 + (p >> 5)) * 8192 + (SWZ(rt * 128 + ((2 * p) & 63) * 2) >> 1);
    __nv_bfloat162 h2, l2;
    split2(t.x, t.y, h2, l2);
    *reinterpret_cast<__nv_bfloat162*>(PLh + e) = h2;
    *reinterpret_cast<__nv_bfloat162*>(PLl + e) = l2;
}
__global__ __launch_bounds__(NT) void head3_k(const float* __restrict__ H2,
                                              float* __restrict__ out) {
    int b = blockIdx.x * NT + threadIdx.x;
    if (b >= BSZ) return;
    const float* h = H2 + (size_t)b * 64;
    float a0 = g_Ba[B3HO], a1 = g_Ba[B3HO + 1];
#pragma unroll
    for (int k = 0; k < 64; k++) {
        float x = h[k];
        a0 += x * g_Ba[W3HO + k];
        a1 += x * g_Ba[W3HO + 64 + k];
    }
    out[b * 2] = a0;
    out[b * 2 + 1] = a1;
}

// ---------------------------------------------------------------------------
extern "C" void kernel_launch(void* const* d_in, const int* in_sizes, int n_in,
                              void* d_out, int out_size) {
    const float* x   = (const float*)d_in[0];
    const float* mw1 = (const float*)d_in[1];
    const float* mb1 = (const float*)d_in[2];
    const float* mw2 = (const float*)d_in[3];
    const float* mb2 = (const float*)d_in[4];
    const float* mw3 = (const float*)d_in[5];
    const float* mb3 = (const float*)d_in[6];
    const float* qw  = (const float*)d_in[7];
    const float* qb  = (const float*)d_in[8];
    const float* kw  = (const float*)d_in[9];
    const float* kb  = (const float*)d_in[10];
    const float* vw  = (const float*)d_in[11];
    const float* vb  = (const float*)d_in[12];
    const float* inw = (const float*)d_in[13];
    const float* inb = (const float*)d_in[14];
    const float* ow  = (const float*)d_in[15];
    const float* ob  = (const float*)d_in[16];
    const float* ow1 = (const float*)d_in[17];
    const float* ob1 = (const float*)d_in[18];
    const float* ow2 = (const float*)d_in[19];
    const float* ob2 = (const float*)d_in[20];
    const float* ow3 = (const float*)d_in[21];
    const float* ob3 = (const float*)d_in[22];
    float* out = (float*)d_out;
    const float s = 0.17677669529663687f;

    char *R0, *R1, *R2, *R3, *RS;
    cudaGetSymbolAddress((void**)&R0, g_R0);
    cudaGetSymbolAddress((void**)&R1, g_R1);
    cudaGetSymbolAddress((void**)&R2, g_R2);
    cudaGetSymbolAddress((void**)&R3, g_R3);
    cudaGetSymbolAddress((void**)&RS, g_RS);

    typedef __nv_bfloat16 bf;
    const size_t E64 = (size_t)MTOT * 64, E256 = (size_t)MTOT * 256;
    // XA:R0 -> gemm12 -> S2:R1 (+SUMF) -> C pipeline (RS) ->
    // FQ reads S2(R1) -> Tq:R0, Tk:R2, Tv:R3
    // Q: Tq(R0)->QH f32(R1)  K: Tk(R2)->KH(R0)  V: Tv(R3)->VH(R2)
    // att(QH,KH,VH)->CX(R3)  out_proj CX(R3)->PLF(maxpool)
    bf *XAh = (bf*)R0, *XAl = XAh + E64;
    bf *S2h = (bf*)R1, *S2l = S2h + E256;
    bf *Tqh = (bf*)R0, *Tql = Tqh + E256;
    bf *Tkh = (bf*)R2, *Tkl = Tkh + E256;
    bf *Tvh = (bf*)R3, *Tvl = Tvh + E256;
    float *QH = (float*)R1;
    float *KH = (float*)R0;
    float *VH = (float*)R2;
    bf *CXh = (bf*)R3, *CXl = CXh + E256;
    bf *PLh = (bf*)(RS + RS_PLH), *PLl = (bf*)(RS + RS_PLL);
    bf *H1h = (bf*)(RS + RS_H1H), *H1l = (bf*)(RS + RS_H1L);
    float *H2 = (float*)(RS + RS_H2);
    float *PLF = (float*)(RS + RS_PLF);
    float *SUMF = (float*)(RS + RS_SUMF);
    bf *SPh = (bf*)(RS + RS_SPH), *SPl = (bf*)(RS + RS_SPL);
    float *CN = (float*)(RS + RS_CN);
    float *scr = (float*)R3;   // fold scratch (prep-time; dead before FQ)

    // ---- prep ----
    fold_k<<<dim3(256, 3), 256>>>(qw, kw, vw, mw3, scr);
    fold_b<<<3, 256>>>(qw, kw, vw, qb, kb, vb, mb3);
    PrepAll pa;
    const float* srcs[9] = {mw1, mw2, scr, inw, inw + 65536, inw + 131072,
                            ow, ow1, ow2};
    int Os[9]   = {128, 256, 768, 256, 256, 256, 256, 128, 64};
    int Ks[9]   = {7, 128, 256, 256, 256, 256, 256, 256, 128};
    int nchs[9] = {1, 2, 4, 4, 4, 4, 4, 4, 2};
    float scs[9] = {1.f, 1.f, -1.f, s, 1.f, 1.f, 1.f, 1.f, 1.f};  // FQ negated
    int offs[9] = {W1OFF, W2OFF, FQOFF, WQOFF, WKOFF, WVOFF, OWOFF, O1OFF, O2OFF};
    for (int i = 0; i < 9; i++) {
        pa.src[i] = srcs[i]; pa.O[i] = Os[i]; pa.K[i] = Ks[i];
        pa.nch[i] = nchs[i]; pa.scale[i] = scs[i]; pa.off[i] = offs[i];
    }
    prep_w_all<<<dim3(64, 9), 256>>>(pa);
    prep_bias<<<1, 256>>>(mb1, mb2, inb, ob, ob1, ob2, ow3, ob3);
    prep_x<<<512, 256>>>(x, XAh, XAl);
    init_misc<<<256, 256>>>(SUMF, PLF);

    cudaFuncSetAttribute(gemm_hmma,
                         cudaFuncAttributeMaxDynamicSharedMemorySize, GSMEM);
    cudaFuncSetAttribute(gemm12_k,
                         cudaFuncAttributeMaxDynamicSharedMemorySize, F_SMEM);
    cudaFuncSetAttribute(att_k, cudaFuncAttributeMaxDynamicSharedMemorySize,
                         ATT_FLOATS * 4);

    const int MT = MTOT / 128;  // 2944
    dim3 GF(2, MT), G256(4, MT), G768(12, MT), GC(12, BSZ / 128),
         GH1(2, BSZ / 128), GH2(1, BSZ / 128);
    bf* Z = nullptr;
    float* F0 = nullptr;
    const float* NC = nullptr;

    gemm12_k<<<GF, NT, F_SMEM>>>(XAh, XAl, S2h, S2l, SUMF);
    vec2pair<<<BSZ, 128>>>(SUMF, SPh, SPl);
    gemm_hmma<<<GC, NT, GSMEM>>>(SPh, SPl, Z, Z, Z, Z, 4, FQOFF, 0, 768,
                                 ZBO, 0, 1, Z, Z, Z, Z, Z, Z, CN, F0, F0,
                                 NC, 0.f);
    gemm_hmma<<<G768, NT, GSMEM>>>(S2h, S2l, Z, Z, Z, Z, 4, FQOFF, 0, 768,
                                   FQB, 1, 0, Tqh, Tql, Tkh, Tkl, Tvh, Tvl,
                                   F0, F0, F0, CN, -1.f);
    gemm_hmma<<<G256, NT, GSMEM>>>(Tqh, Tql, Z, Z, Z, Z, 4, WQOFF, 0, 256,
                                   BQO, 0, 1, Z, Z, Z, Z, Z, Z, QH, F0, F0,
                                   NC, 0.f);
    gemm_hmma<<<G256, NT, GSMEM>>>(Tkh, Tkl, Z, Z, Z, Z, 4, WKOFF, 0, 256,
                                   BKO, 0, 1, Z, Z, Z, Z, Z, Z, KH, F0, F0,
                                   NC, 0.f);
    gemm_hmma<<<G256, NT, GSMEM>>>(Tvh, Tvl, Z, Z, Z, Z, 4, WVOFF, 0, 256,
                                   BVO, 0, 1, Z, Z, Z, Z, Z, Z, VH, F0, F0,
                                   NC, 0.f);
    att_k<<<BSZ, NT, ATT_FLOATS * 4>>>(QH, KH, VH, CXh, CXl);
    gemm_hmma<<<G256, NT, GSMEM>>>(CXh, CXl, Z, Z, Z, Z, 4, OWOFF, 0, 256,
                                   OBO, 0, 2, Z, Z, Z, Z, Z, Z, PLF, F0, F0,
                                   NC, 0.f);
    pool2pair<<<BSZ, 128>>>(PLF, PLh, PLl);
    gemm_hmma<<<GH1, NT, GSMEM>>>(PLh, PLl, Z, Z, Z, Z, 4, O1OFF, 0, 128,
                                  OB1O, 1, 0, H1h, H1l, Z, Z, Z, Z, F0, F0, F0,
                                  NC, 0.f);
    gemm_hmma<<<GH2, NT, GSMEM>>>(H1h, H1l, Z, Z, Z, Z, 2, O2OFF, 0, 64,
                                  OB2O, 1, 1, Z, Z, Z, Z, Z, Z, H2, F0, F0,
                                  NC, 0.f);
    head3_k<<<BSZ / NT, NT>>>(H2, out);
}

// round 17
// speedup vs baseline: 1.0277x; 1.0277x over previous
#include <cuda_runtime.h>
#include <cuda_bf16.h>
#include <cstdint>

#define NN 23
#define BSZ 16384
#define MTOT (BSZ * NN)          // 376832 = 2944*128
#define NT 256
#define SWZ(o) ((o) ^ (((o) >> 3) & 0x70))

// ---------------- 4 big aliased regions + 1 small region -------------------
#define REGB ((size_t)MTOT * 256 * 4)
__device__ __align__(128) char g_R0[REGB];
__device__ __align__(128) char g_R1[REGB];
__device__ __align__(128) char g_R2[REGB];
__device__ __align__(128) char g_R3[REGB];
#define RS_PLH 0
#define RS_PLL ((size_t)BSZ * 256 * 2)
#define RS_H1H ((size_t)BSZ * 256 * 4)
#define RS_H1L (RS_H1H + (size_t)BSZ * 128 * 2)
#define RS_PLF (RS_H1H + (size_t)BSZ * 128 * 4)
#define RS_SZ  (RS_PLF + (size_t)BSZ * 256 * 4)
__device__ __align__(128) char g_RS[RS_SZ];

// ---------------- weight arena (pre-swizzled chunk images), elem offsets
#define W1OFF 0
#define W2OFF 8192
#define FQOFF 40960              // fused folded QKV: O=768, nch=4
#define WQOFF 237568
#define WKOFF 303104
#define WVOFF 368640
#define OWOFF 434176
#define O1OFF 499712
#define O2OFF 532480
#define WSZ   540672
__device__ __align__(16) __nv_bfloat16 g_Wh[WSZ];
__device__ __align__(16) __nv_bfloat16 g_Wl[WSZ];

// bias arena (f32) + head3 weights + folded qkv bias (768 @ FQB)
#define B1O 0
#define B2O 128
#define BQO 1408
#define BKO 1664
#define BVO 1920
#define OBO 2176
#define OB1O 2432
#define OB2O 2560
#define W3HO 2624
#define B3HO 2752
#define FQB 3072
__device__ float g_Ba[4096];

// ---------------- helpers
__device__ __forceinline__ unsigned smem_u32(const void* p) {
    return (unsigned)__cvta_generic_to_shared(p);
}
__device__ __forceinline__ void ldm4(uint32_t* r, unsigned a) {
    asm volatile("ldmatrix.sync.aligned.m8n8.x4.shared.b16 {%0,%1,%2,%3}, [%4];"
                 : "=r"(r[0]), "=r"(r[1]), "=r"(r[2]), "=r"(r[3]) : "r"(a));
}
__device__ __forceinline__ void mma16816(float* c, const uint32_t* a,
                                         const uint32_t* b) {
    asm volatile(
        "mma.sync.aligned.m16n8k16.row.col.f32.bf16.bf16.f32 "
        "{%0,%1,%2,%3},{%4,%5,%6,%7},{%8,%9},{%0,%1,%2,%3};"
        : "+f"(c[0]), "+f"(c[1]), "+f"(c[2]), "+f"(c[3])
        : "r"(a[0]), "r"(a[1]), "r"(a[2]), "r"(a[3]), "r"(b[0]), "r"(b[1]));
}
__device__ __forceinline__ void split2(float a, float b,
                                       __nv_bfloat162& h2, __nv_bfloat162& l2) {
    __nv_bfloat16 ah = __float2bfloat16(a), bh = __float2bfloat16(b);
    h2 = __halves2bfloat162(ah, bh);
    l2 = __halves2bfloat162(__float2bfloat16(a - __bfloat162float(ah)),
                            __float2bfloat16(b - __bfloat162float(bh)));
}
__device__ __forceinline__ void bulk_cp(unsigned d, const void* s,
                                        unsigned bytes, unsigned mbar) {
    asm volatile(
        "cp.async.bulk.shared::cluster.global.mbarrier::complete_tx::bytes "
        "[%0], [%1], %2, [%3];"
        :: "r"(d), "l"(s), "r"(bytes), "r"(mbar) : "memory");
}
__device__ __forceinline__ void mbar_wait(unsigned m, int par) {
    uint32_t done;
    asm volatile("{\n\t.reg .pred p;\n\t"
                 "mbarrier.try_wait.parity.acquire.cta.shared::cta.b64 p, [%1], %2;\n\t"
                 "selp.b32 %0,1,0,p;\n\t}"
                 : "=r"(done) : "r"(m), "r"((uint32_t)par) : "memory");
    if (!done)
        asm volatile("{\n\t.reg .pred P1;\n\tWL_%=:\n\t"
                     "mbarrier.try_wait.parity.acquire.cta.shared::cta.b64 P1, [%0], %1, 0x989680;\n\t"
                     "@P1 bra.uni WD_%=;\n\tbra.uni WL_%=;\n\tWD_%=:\n\t}"
                     :: "r"(m), "r"((uint32_t)par) : "memory");
}

// ---------------- fold kernels: F_g = w_g @ W3 ; fb = b_g + 22*w_g@b3 ------
__global__ void fold_k(const float* __restrict__ qw, const float* __restrict__ kw,
                       const float* __restrict__ vw, const float* __restrict__ w3,
                       float* __restrict__ scr) {
    int r = blockIdx.x, g = blockIdx.y, t = threadIdx.x;
    __shared__ float row[256];
    const float* w = g == 0 ? qw : (g == 1 ? kw : vw);
    row[t] = w[r * 256 + t];
    __syncthreads();
    float a = 0.f;
#pragma unroll 8
    for (int j = 0; j < 256; j++) a += row[j] * w3[j * 256 + t];
    scr[((size_t)(g * 256 + r)) * 256 + t] = a;
}
__global__ void fold_b(const float* qw, const float* kw, const float* vw,
                       const float* qb, const float* kb, const float* vb,
                       const float* b3) {
    int o = blockIdx.x * 256 + threadIdx.x;
    int g = o >> 8, r = o & 255;
    const float* w = g == 0 ? qw : (g == 1 ? kw : vw);
    const float* b = g == 0 ? qb : (g == 1 ? kb : vb);
    float a = 0.f;
#pragma unroll 8
    for (int j = 0; j < 256; j++) a += w[r * 256 + j] * b3[j];
    g_Ba[FQB + o] = b[r] + 22.f * a;
}

// ---------------- merged weight prep: 9 segments in one launch -------------
struct PrepAll {
    const float* src[9];
    int O[9], K[9], nch[9];
    float scale[9];
    int off[9];
};
__global__ void prep_w_all(PrepAll pa) {
    int seg = blockIdx.y;
    const float* __restrict__ src = pa.src[seg];
    int O = pa.O[seg], K = pa.K[seg], nch = pa.nch[seg], off = pa.off[seg];
    float scale = pa.scale[seg];
    int tot = nch * O * 64;
    for (int e = blockIdx.x * blockDim.x + threadIdx.x; e < tot;
         e += gridDim.x * blockDim.x) {
        int kc = e / (O * 64), rem = e - kc * O * 64;
        int r = rem >> 6, kk = rem & 63, k = kc * 64 + kk;
        float v = (k < K) ? src[(size_t)r * K + k] * scale : 0.f;
        __nv_bfloat16 h = __float2bfloat16(v);
        int dst = off + kc * O * 64 + (SWZ(r * 128 + kk * 2) >> 1);
        g_Wh[dst] = h;
        g_Wl[dst] = __float2bfloat16(v - __bfloat162float(h));
    }
}
__global__ void prep_x(const float* __restrict__ x,
                       __nv_bfloat16* __restrict__ XAh,
                       __nv_bfloat16* __restrict__ XAl) {
    for (size_t e = (size_t)blockIdx.x * blockDim.x + threadIdx.x;
         e < (size_t)MTOT * 64; e += (size_t)gridDim.x * blockDim.x) {
        size_t m = e >> 6;
        int c = (int)(e & 63);
        float v = (c < 7) ? x[m * 7 + c] : 0.f;
        size_t tile = m >> 7;
        int rt = (int)(m & 127);
        size_t dst = tile * 8192 + (SWZ(rt * 128 + c * 2) >> 1);
        __nv_bfloat16 h = __float2bfloat16(v);
        XAh[dst] = h;
        XAl[dst] = __float2bfloat16(v - __bfloat162float(h));
    }
}
__global__ void prep_bias(const float* b1, const float* b2,
                          const float* inb, const float* ob, const float* ob1,
                          const float* ob2, const float* ow3, const float* ob3) {
    const float s = 0.17677669529663687f;
    int t = threadIdx.x;
    for (int i = t; i < 128; i += 256) g_Ba[B1O + i] = b1[i];
    for (int i = t; i < 256; i += 256) g_Ba[B2O + i] = b2[i];
    for (int i = t; i < 256; i += 256) g_Ba[BQO + i] = inb[i] * s;
    for (int i = t; i < 256; i += 256) g_Ba[BKO + i] = inb[256 + i];
    for (int i = t; i < 256; i += 256) g_Ba[BVO + i] = inb[512 + i];
    for (int i = t; i < 256; i += 256) g_Ba[OBO + i] = ob[i];
    for (int i = t; i < 128; i += 256) g_Ba[OB1O + i] = ob1[i];
    for (int i = t; i < 64;  i += 256) g_Ba[OB2O + i] = ob2[i];
    for (int i = t; i < 128; i += 256) g_Ba[W3HO + i] = ow3[i];
    for (int i = t; i < 2;   i += 256) g_Ba[B3HO + i] = ob3[i];
}
__global__ void init_pool(float* __restrict__ PLF) {
    for (size_t i = (size_t)blockIdx.x * blockDim.x + threadIdx.x;
         i < (size_t)BSZ * 256; i += (size_t)gridDim.x * blockDim.x)
        reinterpret_cast<unsigned*>(PLF)[i] = 0xff800000u;  // -inf
}
__global__ __launch_bounds__(128) void pool2pair(const float* __restrict__ PLF,
                                                 __nv_bfloat16* __restrict__ PLh,
                                                 __nv_bfloat16* __restrict__ PLl) {
    int b = blockIdx.x, p = threadIdx.x;
    float2 t = *reinterpret_cast<const float2*>(PLF + (size_t)b * 256 + 2 * p);
    size_t tile = b >> 7; int rt = b & 127;
    size_t e = (tile * 4 + (p >> 5)) * 8192 + (SWZ(rt * 128 + ((2 * p) & 63) * 2) >> 1);
    __nv_bfloat162 h2, l2;
    split2(t.x, t.y, h2, l2);
    *reinterpret_cast<__nv_bfloat162*>(PLh + e) = h2;
    *reinterpret_cast<__nv_bfloat162*>(PLl + e) = l2;
}

// ---------------------------------------------------------------------------
// HMMA GEMM: CTA tile M=128 x 64, K = nch*64, 3-term bf16 split, occ 2,
// 2-stage cp.async.bulk ring.
// outmode: 0 = bf16 pair image, 1 = f32 plane, 2 = fused maxpool (atomics),
//          3 = fused final head (rows = batches; writes out[b*2+{0,1}]).
// ---------------------------------------------------------------------------
#define BUFB 49152
#define GSMEM (1024 + 2 * BUFB + 64)
__global__ void __launch_bounds__(NT, 2) gemm_hmma(
    const __nv_bfloat16* __restrict__ Ah_, const __nv_bfloat16* __restrict__ Al_,
    const __nv_bfloat16* __restrict__ Ah1_, const __nv_bfloat16* __restrict__ Al1_,
    const __nv_bfloat16* __restrict__ Ah2_, const __nv_bfloat16* __restrict__ Al2_,
    int nch, int woff, int wzs, int Nfull, int boff, int act, int outmode,
    __nv_bfloat16* __restrict__ Oh, __nv_bfloat16* __restrict__ Ol,
    __nv_bfloat16* __restrict__ Oh1, __nv_bfloat16* __restrict__ Ol1,
    __nv_bfloat16* __restrict__ Oh2, __nv_bfloat16* __restrict__ Ol2,
    float* __restrict__ Of, float* __restrict__ Of1, float* __restrict__ Of2) {
    extern __shared__ char smem[];
    const unsigned sb = (smem_u32(smem) + 1023u) & ~1023u;
    char* scm = smem + (sb - smem_u32(smem));
    const unsigned mb0 = sb + 2 * BUFB, mb1 = mb0 + 8;
    const int tid = threadIdx.x, w = tid >> 5, l = tid & 31;
    const int m0 = (w >> 1) * 32, n0l = (w & 1) * 32;
    const int n0g = blockIdx.x * 64;
    const int mt = blockIdx.y;
    const int z = blockIdx.z;
    const __nv_bfloat16* Ahp = z == 0 ? Ah_ : (z == 1 ? Ah1_ : Ah2_);
    const __nv_bfloat16* Alp = z == 0 ? Al_ : (z == 1 ? Al1_ : Al2_);
    float* Ofz = z == 0 ? Of : (z == 1 ? Of1 : Of2);
    const int woz = woff + z * wzs, boz = boff + z * 256;

    float acc[2][4][4];
#pragma unroll
    for (int mi = 0; mi < 2; mi++)
#pragma unroll
        for (int nj = 0; nj < 4; nj++)
#pragma unroll
            for (int q = 0; q < 4; q++) acc[mi][nj][q] = 0.f;

    if (tid == 0) {
        asm volatile("mbarrier.init.shared.b64 [%0], 1;" :: "r"(mb0) : "memory");
        asm volatile("mbarrier.init.shared.b64 [%0], 1;" :: "r"(mb1) : "memory");
    }
    __syncthreads();

    auto stage = [&](int c) {
        if (tid == 0) {
            size_t ao = ((size_t)mt * nch + c) * 16384;
            size_t bo = ((size_t)woz + (size_t)c * Nfull * 64 +
                         (size_t)n0g * 64) * 2;
            unsigned d = sb + (unsigned)(c & 1) * BUFB;
            unsigned mb = (c & 1) ? mb1 : mb0;
            asm volatile("mbarrier.arrive.expect_tx.shared.b64 _, [%0], %1;"
                         :: "r"(mb), "r"(49152u) : "memory");
            bulk_cp(d, (const char*)Ahp + ao, 16384, mb);
            bulk_cp(d + 16384, (const char*)Alp + ao, 16384, mb);
            bulk_cp(d + 32768, (const char*)g_Wh + bo, 8192, mb);
            bulk_cp(d + 40960, (const char*)g_Wl + bo, 8192, mb);
        }
    };

    stage(0);
    if (nch > 1) stage(1);

    const int rowA = l & 15, kA = (l >> 4) * 8;
    const int nB = (l & 7) + ((l >> 4) & 1) * 8, kB = ((l >> 3) & 1) * 8;
    const unsigned offA0 = SWZ((m0 + rowA) * 128 + kA * 2);
    const unsigned offA1 = SWZ((m0 + 16 + rowA) * 128 + kA * 2);
    const unsigned offB0 = SWZ((n0l + nB) * 128 + kB * 2);
    const unsigned offB1 = SWZ((n0l + 16 + nB) * 128 + kB * 2);

    int par0 = 0, par1 = 0;
    for (int c = 0; c < nch; c++) {
        if ((c & 1) == 0) { mbar_wait(mb0, par0); par0 ^= 1; }
        else              { mbar_wait(mb1, par1); par1 ^= 1; }

        const unsigned bb = sb + (unsigned)(c & 1) * BUFB;
        const unsigned aH0 = bb + offA0, aH1 = bb + offA1;
        const unsigned aL0 = aH0 + 16384, aL1 = aH1 + 16384;
        const unsigned bH0 = bb + 32768 + offB0, bH1 = bb + 32768 + offB1;
        const unsigned bL0 = bH0 + 8192, bL1 = bH1 + 8192;

#pragma unroll
        for (int ks = 0; ks < 4; ks++) {
            const unsigned kx = (unsigned)(ks << 5);
            uint32_t ah[2][4], al[2][4];
            ldm4(ah[0], aH0 ^ kx);
            ldm4(al[0], aL0 ^ kx);
            ldm4(ah[1], aH1 ^ kx);
            ldm4(al[1], aL1 ^ kx);
#pragma unroll
            for (int g = 0; g < 2; g++) {
                uint32_t rh[4], rl[4];
                ldm4(rh, (g ? bH1 : bH0) ^ kx);
                ldm4(rl, (g ? bL1 : bL0) ^ kx);
#pragma unroll
                for (int mi = 0; mi < 2; mi++) {
                    mma16816(acc[mi][2 * g], ah[mi], rh);
                    mma16816(acc[mi][2 * g], al[mi], rh);
                    mma16816(acc[mi][2 * g], ah[mi], rl);
                    mma16816(acc[mi][2 * g + 1], ah[mi], rh + 2);
                    mma16816(acc[mi][2 * g + 1], al[mi], rh + 2);
                    mma16816(acc[mi][2 * g + 1], ah[mi], rl + 2);
                }
            }
        }
        __syncthreads();
        if (c + 2 < nch) stage(c + 2);
    }

    // ---- epilogue ----
    const int rq = l >> 2, cq = (l & 3) * 2;
    if (outmode == 0) {
#pragma unroll
        for (int mi = 0; mi < 2; mi++)
#pragma unroll
            for (int nj = 0; nj < 4; nj++) {
                int lc = n0l + nj * 8 + cq;
                int cg = n0g + lc;
                float b0 = g_Ba[boz + cg], b1 = g_Ba[boz + cg + 1];
                float v[4] = {acc[mi][nj][0] + b0, acc[mi][nj][1] + b1,
                              acc[mi][nj][2] + b0, acc[mi][nj][3] + b1};
                if (act) {
#pragma unroll
                    for (int q = 0; q < 4; q++)
                        v[q] = v[q] >= 0.f ? v[q] : 0.2f * v[q];
                }
                int r0 = m0 + mi * 16 + rq, r1 = r0 + 8;
                int e0 = SWZ(r0 * 128 + lc * 2), e1 = SWZ(r1 * 128 + lc * 2);
                __nv_bfloat162 h2, l2;
                split2(v[0], v[1], h2, l2);
                *reinterpret_cast<__nv_bfloat162*>(scm + e0) = h2;
                *reinterpret_cast<__nv_bfloat162*>(scm + 16384 + e0) = l2;
                split2(v[2], v[3], h2, l2);
                *reinterpret_cast<__nv_bfloat162*>(scm + e1) = h2;
                *reinterpret_cast<__nv_bfloat162*>(scm + 16384 + e1) = l2;
            }
        __syncthreads();
        int grp = n0g >> 8, lc0 = n0g & 255;
        __nv_bfloat16* OH = grp == 0 ? Oh : (grp == 1 ? Oh1 : Oh2);
        __nv_bfloat16* OL = grp == 0 ? Ol : (grp == 1 ? Ol1 : Ol2);
        const int nchO = (Nfull >= 256 ? 4 : (Nfull >> 6));
        size_t baseB = (((size_t)mt * nchO + (lc0 >> 6)) * 8192) * 2;
        char* dH = (char*)OH + baseB;
        char* dL = (char*)OL + baseB;
        for (int i = tid * 16; i < 16384; i += NT * 16) {
            *reinterpret_cast<float4*>(dH + i) =
                *reinterpret_cast<const float4*>(scm + i);
            *reinterpret_cast<float4*>(dL + i) =
                *reinterpret_cast<const float4*>(scm + 16384 + i);
        }
    } else {
        float* st = (float*)scm;  // row stride 68 floats
#pragma unroll
        for (int mi = 0; mi < 2; mi++)
#pragma unroll
            for (int nj = 0; nj < 4; nj++) {
                int lc = n0l + nj * 8 + cq;
                int cg = n0g + lc;
                float b0 = g_Ba[boz + cg], b1 = g_Ba[boz + cg + 1];
                float v[4] = {acc[mi][nj][0] + b0, acc[mi][nj][1] + b1,
                              acc[mi][nj][2] + b0, acc[mi][nj][3] + b1};
                if (act) {
#pragma unroll
                    for (int q = 0; q < 4; q++)
                        v[q] = v[q] >= 0.f ? v[q] : 0.2f * v[q];
                }
                int r0 = m0 + mi * 16 + rq, r1 = r0 + 8;
                st[r0 * 68 + lc] = v[0];
                st[r0 * 68 + lc + 1] = v[1];
                st[r1 * 68 + lc] = v[2];
                st[r1 * 68 + lc + 1] = v[3];
            }
        __syncthreads();
        if (outmode == 1) {
            size_t m0r = (size_t)mt * 128;
            for (int idx = tid; idx < 2048; idx += NT) {
                int row = idx >> 4, qq = idx & 15;
                float4 vv = *reinterpret_cast<const float4*>(st + row * 68 + qq * 4);
                *reinterpret_cast<float4*>(Ofz + (m0r + row) * Nfull + n0g + qq * 4) = vv;
            }
        } else if (outmode == 2) {  // fused maxpool over node rows
            const int mr0 = mt * 128;
            const int bfirst = mr0 / NN;
            const int blast = (mr0 + 127) / NN;
            const int nb = blast - bfirst + 1;
            for (int idx = tid; idx < nb * 64; idx += NT) {
                int bl = idx >> 6, col = idx & 63;
                int b = bfirst + bl;
                int rlo = b * NN, rhi = rlo + NN;
                if (rlo < mr0) rlo = mr0;
                if (rhi > mr0 + 128) rhi = mr0 + 128;
                float mx = -1e30f;
                for (int r = rlo; r < rhi; r++)
                    mx = fmaxf(mx, st[(r - mr0) * 68 + col]);
                float* p = Ofz + (size_t)b * 256 + n0g + col;
                if (mx >= 0.f)
                    atomicMax(reinterpret_cast<int*>(p), __float_as_int(mx));
                else
                    atomicMin(reinterpret_cast<unsigned*>(p), __float_as_uint(mx));
            }
        } else {  // outmode == 3: fused final head (rows = batches, N=64)
            for (int idx = tid; idx < 256; idx += NT) {
                int row = idx >> 1, o = idx & 1;
                float a = g_Ba[B3HO + o];
                const float* h = st + row * 68;
                const float* w3 = g_Ba + W3HO + o * 64;
#pragma unroll 16
                for (int k = 0; k < 64; k++) a += h[k] * w3[k];
                Ofz[((size_t)mt * 128 + row) * 2 + o] = a;
            }
        }
    }
}

// ---------------------------------------------------------------------------
// FUSED layer1+layer2 (R15 version)
// ---------------------------------------------------------------------------
#define F_SMEM (1024 + 65536 + 32768 + 64)
__global__ void __launch_bounds__(NT, 2) gemm12_k(
    const __nv_bfloat16* __restrict__ XAh, const __nv_bfloat16* __restrict__ XAl,
    __nv_bfloat16* __restrict__ Oh, __nv_bfloat16* __restrict__ Ol) {
    extern __shared__ char smem[];
    const unsigned sb = (smem_u32(smem) + 1023u) & ~1023u;
    char* scm = smem + (sb - smem_u32(smem));
    const unsigned R0 = sb, R1 = sb + 65536;
    const unsigned mb0 = sb + 98304, mb1 = mb0 + 8;
    const int tid = threadIdx.x, w = tid >> 5, l = tid & 31;
    const int m0 = (w >> 1) * 32, n0l = (w & 1) * 64;
    const int n0g = blockIdx.x * 128;
    const int mt = blockIdx.y;

    if (tid == 0) {
        asm volatile("mbarrier.init.shared.b64 [%0], 1;" :: "r"(mb0) : "memory");
        asm volatile("mbarrier.init.shared.b64 [%0], 1;" :: "r"(mb1) : "memory");
    }
    __syncthreads();

    if (tid == 0) {
        size_t ao = (size_t)mt * 16384;
        asm volatile("mbarrier.arrive.expect_tx.shared.b64 _, [%0], %1;"
                     :: "r"(mb0), "r"(65536u) : "memory");
        bulk_cp(R0, (const char*)XAh + ao, 16384, mb0);
        bulk_cp(R0 + 16384, (const char*)XAl + ao, 16384, mb0);
        bulk_cp(R0 + 32768, (const char*)g_Wh + (size_t)W1OFF * 2, 16384, mb0);
        bulk_cp(R0 + 49152, (const char*)g_Wl + (size_t)W1OFF * 2, 16384, mb0);
        size_t bo = ((size_t)W2OFF + (size_t)n0g * 64) * 2;
        asm volatile("mbarrier.arrive.expect_tx.shared.b64 _, [%0], %1;"
                     :: "r"(mb1), "r"(32768u) : "memory");
        bulk_cp(R1, (const char*)g_Wh + bo, 16384, mb1);
        bulk_cp(R1 + 16384, (const char*)g_Wl + bo, 16384, mb1);
    }

    const int rowA = l & 15, kA = (l >> 4) * 8;
    const int nB = (l & 7) + ((l >> 4) & 1) * 8, kB = ((l >> 3) & 1) * 8;
    const unsigned offA0 = SWZ((m0 + rowA) * 128 + kA * 2);
    const unsigned offA1 = SWZ((m0 + 16 + rowA) * 128 + kA * 2);
    unsigned offB[4];
#pragma unroll
    for (int g = 0; g < 4; g++)
        offB[g] = SWZ((n0l + g * 16 + nB) * 128 + kB * 2);

    float acc[2][8][4];
#pragma unroll
    for (int mi = 0; mi < 2; mi++)
#pragma unroll
        for (int nj = 0; nj < 8; nj++)
#pragma unroll
            for (int q = 0; q < 4; q++) acc[mi][nj][q] = 0.f;

    // ---- phase 1: S1 = lrelu(XA @ W1 + b1), K=64 ----
    mbar_wait(mb0, 0);
    {
        const unsigned aH0 = R0 + offA0, aH1 = R0 + offA1;
        const unsigned aL0 = aH0 + 16384, aL1 = aH1 + 16384;
#pragma unroll
        for (int ks = 0; ks < 4; ks++) {
            const unsigned kx = (unsigned)(ks << 5);
            uint32_t ah[2][4], al[2][4];
            ldm4(ah[0], aH0 ^ kx);
            ldm4(al[0], aL0 ^ kx);
            ldm4(ah[1], aH1 ^ kx);
            ldm4(al[1], aL1 ^ kx);
#pragma unroll
            for (int g = 0; g < 4; g++) {
                const unsigned bH = R0 + 32768 + offB[g];
                const unsigned bL = bH + 16384;
                uint32_t rh[4], rl[4];
                ldm4(rh, bH ^ kx);
                ldm4(rl, bL ^ kx);
#pragma unroll
                for (int mi = 0; mi < 2; mi++) {
                    mma16816(acc[mi][2 * g], ah[mi], rh);
                    mma16816(acc[mi][2 * g], al[mi], rh);
                    mma16816(acc[mi][2 * g], ah[mi], rl);
                    mma16816(acc[mi][2 * g + 1], ah[mi], rh + 2);
                    mma16816(acc[mi][2 * g + 1], al[mi], rh + 2);
                    mma16816(acc[mi][2 * g + 1], ah[mi], rl + 2);
                }
            }
        }
    }
    __syncthreads();

    // ---- write S1 image into R0 ----
    const int rq = l >> 2, cq = (l & 3) * 2;
#pragma unroll
    for (int mi = 0; mi < 2; mi++)
#pragma unroll
        for (int nj = 0; nj < 8; nj++) {
            int lc = n0l + nj * 8 + cq;
            float b0 = g_Ba[B1O + lc], b1 = g_Ba[B1O + lc + 1];
            float v[4] = {acc[mi][nj][0] + b0, acc[mi][nj][1] + b1,
                          acc[mi][nj][2] + b0, acc[mi][nj][3] + b1};
#pragma unroll
            for (int q = 0; q < 4; q++) v[q] = v[q] >= 0.f ? v[q] : 0.2f * v[q];
            int r0 = m0 + mi * 16 + rq, r1 = r0 + 8;
            int ch = lc >> 6, cc = lc & 63;
            unsigned e0 = (unsigned)ch * 16384 + SWZ(r0 * 128 + cc * 2);
            unsigned e1 = (unsigned)ch * 16384 + SWZ(r1 * 128 + cc * 2);
            __nv_bfloat162 h2, l2;
            split2(v[0], v[1], h2, l2);
            *reinterpret_cast<__nv_bfloat162*>(scm + e0) = h2;
            *reinterpret_cast<__nv_bfloat162*>(scm + e0 + 32768) = l2;
            split2(v[2], v[3], h2, l2);
            *reinterpret_cast<__nv_bfloat162*>(scm + e1) = h2;
            *reinterpret_cast<__nv_bfloat162*>(scm + e1 + 32768) = l2;
        }
    __syncthreads();

    // ---- phase 2: S2 slice = lrelu(S1 @ W2_slice + b2), K=128 ----
#pragma unroll
    for (int mi = 0; mi < 2; mi++)
#pragma unroll
        for (int nj = 0; nj < 8; nj++)
#pragma unroll
            for (int q = 0; q < 4; q++) acc[mi][nj][q] = 0.f;

    int par1 = 0;
    for (int c = 0; c < 2; c++) {
        mbar_wait(mb1, par1);
        par1 ^= 1;
        const unsigned aH0 = R0 + c * 16384 + offA0;
        const unsigned aH1 = R0 + c * 16384 + offA1;
        const unsigned aL0 = aH0 + 32768, aL1 = aH1 + 32768;
#pragma unroll
        for (int ks = 0; ks < 4; ks++) {
            const unsigned kx = (unsigned)(ks << 5);
            uint32_t ah[2][4], al[2][4];
            ldm4(ah[0], aH0 ^ kx);
            ldm4(al[0], aL0 ^ kx);
            ldm4(ah[1], aH1 ^ kx);
            ldm4(al[1], aL1 ^ kx);
#pragma unroll
            for (int g = 0; g < 4; g++) {
                const unsigned bH = R1 + offB[g];
                const unsigned bL = bH + 16384;
                uint32_t rh[4], rl[4];
                ldm4(rh, bH ^ kx);
                ldm4(rl, bL ^ kx);
#pragma unroll
                for (int mi = 0; mi < 2; mi++) {
                    mma16816(acc[mi][2 * g], ah[mi], rh);
                    mma16816(acc[mi][2 * g], al[mi], rh);
                    mma16816(acc[mi][2 * g], ah[mi], rl);
                    mma16816(acc[mi][2 * g + 1], ah[mi], rh + 2);
                    mma16816(acc[mi][2 * g + 1], al[mi], rh + 2);
                    mma16816(acc[mi][2 * g + 1], ah[mi], rl + 2);
                }
            }
        }
        __syncthreads();
        if (c == 0 && tid == 0) {
            size_t bo = ((size_t)W2OFF + (size_t)256 * 64 + (size_t)n0g * 64) * 2;
            asm volatile("mbarrier.arrive.expect_tx.shared.b64 _, [%0], %1;"
                         :: "r"(mb1), "r"(32768u) : "memory");
            bulk_cp(R1, (const char*)g_Wh + bo, 16384, mb1);
            bulk_cp(R1 + 16384, (const char*)g_Wl + bo, 16384, mb1);
        }
    }

    // ---- epilogue ----
#pragma unroll
    for (int mi = 0; mi < 2; mi++)
#pragma unroll
        for (int nj = 0; nj < 8; nj++) {
            int lc = n0l + nj * 8 + cq;
            int cg = n0g + lc;
            float b0 = g_Ba[B2O + cg], b1 = g_Ba[B2O + cg + 1];
            float v[4] = {acc[mi][nj][0] + b0, acc[mi][nj][1] + b1,
                          acc[mi][nj][2] + b0, acc[mi][nj][3] + b1};
#pragma unroll
            for (int q = 0; q < 4; q++) v[q] = v[q] >= 0.f ? v[q] : 0.2f * v[q];
            int r0 = m0 + mi * 16 + rq, r1 = r0 + 8;
            int ch = lc >> 6, cc = lc & 63;
            unsigned base = (unsigned)ch * 32768;
            unsigned e0 = base + SWZ(r0 * 128 + cc * 2);
            unsigned e1 = base + SWZ(r1 * 128 + cc * 2);
            __nv_bfloat162 h2, l2;
            split2(v[0], v[1], h2, l2);
            *reinterpret_cast<__nv_bfloat162*>(scm + e0) = h2;
            *reinterpret_cast<__nv_bfloat162*>(scm + e0 + 16384) = l2;
            split2(v[2], v[3], h2, l2);
            *reinterpret_cast<__nv_bfloat162*>(scm + e1) = h2;
            *reinterpret_cast<__nv_bfloat162*>(scm + e1 + 16384) = l2;
        }
    __syncthreads();
    for (int ch = 0; ch < 2; ch++) {
        size_t baseB = (((size_t)mt * 4 + (n0g >> 6) + ch) * 8192) * 2;
        char* dH = (char*)Oh + baseB;
        char* dL = (char*)Ol + baseB;
        const char* sB = scm + ch * 32768;
        for (int i = tid * 16; i < 16384; i += NT * 16) {
            *reinterpret_cast<float4*>(dH + i) =
                *reinterpret_cast<const float4*>(sB + i);
            *reinterpret_cast<float4*>(dL + i) =
                *reinterpret_cast<const float4*>(sB + 16384 + i);
        }
    }
}

// ---------------- agg in h2-space: G_n = sum_m h2_m - h2_n -----------------
__global__ __launch_bounds__(128) void agg2_k(const __nv_bfloat16* __restrict__ S2h,
                                              const __nv_bfloat16* __restrict__ S2l,
                                              __nv_bfloat16* __restrict__ Gh,
                                              __nv_bfloat16* __restrict__ Gl) {
    int b = blockIdx.x, p = threadIdx.x;
    int chunk = p >> 5, cc = (2 * p) & 63;
    float2 v[NN];
    float sx = 0.f, sy = 0.f;
    size_t eo[NN];
#pragma unroll
    for (int n = 0; n < NN; n++) {
        size_t m = (size_t)b * NN + n;
        size_t tile = m >> 7; int rt = (int)(m & 127);
        size_t e = (tile * 4 + chunk) * 8192 + (SWZ(rt * 128 + cc * 2) >> 1);
        eo[n] = e;
        __nv_bfloat162 h2 = *reinterpret_cast<const __nv_bfloat162*>(S2h + e);
        __nv_bfloat162 l2 = *reinterpret_cast<const __nv_bfloat162*>(S2l + e);
        v[n] = make_float2(__bfloat162float(h2.x) + __bfloat162float(l2.x),
                           __bfloat162float(h2.y) + __bfloat162float(l2.y));
        sx += v[n].x; sy += v[n].y;
    }
#pragma unroll
    for (int n = 0; n < NN; n++) {
        __nv_bfloat162 h2, l2;
        split2(sx - v[n].x, sy - v[n].y, h2, l2);
        *reinterpret_cast<__nv_bfloat162*>(Gh + eo[n]) = h2;
        *reinterpret_cast<__nv_bfloat162*>(Gl + eo[n]) = l2;
    }
}

// ---------------- attention per batch (fp32), ctx -> swz bf16 pair
#define ATT_FLOATS (5888 + 6144 + 5888 + 4416)
__global__ __launch_bounds__(NT) void att_k(const float* __restrict__ QH,
                                            const float* __restrict__ KH,
                                            const float* __restrict__ VH,
                                            __nv_bfloat16* __restrict__ CXh,
                                            __nv_bfloat16* __restrict__ CXl) {
    extern __shared__ float sm[];
    float* q = sm;
    float* kT = q + 5888;
    float* v = kT + 6144;
    float* S = v + 5888;
    const int tid = threadIdx.x, b = blockIdx.x;
    const size_t base = (size_t)b * NN * 256;

    for (int i = tid; i < 1472; i += NT) {
        reinterpret_cast<float4*>(q)[i] = reinterpret_cast<const float4*>(QH + base)[i];
        reinterpret_cast<float4*>(v)[i] = reinterpret_cast<const float4*>(VH + base)[i];
    }
    for (int i = tid; i < 5888; i += NT) {
        int m = i >> 8, c = i & 255;
        kT[c * 24 + m] = KH[base + (size_t)m * 256 + c];
    }
    __syncthreads();

    int w = tid >> 5, lane = tid & 31;
    for (int task = w; task < 184; task += 8) {
        int h = task / 23, n = task - h * 23;
        const float* qr = q + n * 256 + h * 32;
        float a = 0.f;
        if (lane < NN) {
#pragma unroll
            for (int d = 0; d < 32; d++) a += qr[d] * kT[(h * 32 + d) * 24 + lane];
        }
        float mx = (lane < NN) ? a : -1e30f;
#pragma unroll
        for (int o = 16; o; o >>= 1) mx = fmaxf(mx, __shfl_xor_sync(~0u, mx, o));
        float e = (lane < NN) ? __expf(a - mx) : 0.f;
        float s = e;
#pragma unroll
        for (int o = 16; o; o >>= 1) s += __shfl_xor_sync(~0u, s, o);
        if (lane < NN) S[h * 552 + n * 24 + lane] = e / s;
    }
    __syncthreads();

    for (int idx = tid; idx < NN * 128; idx += NT) {
        int n = idx >> 7, p = idx & 127, h = p >> 4;
        const float* Sr = S + h * 552 + n * 24;
        const float* vc = v + 2 * p;
        float ax = 0.f, ay = 0.f;
#pragma unroll
        for (int m = 0; m < NN; m++) {
            float s = Sr[m];
            ax += s * vc[m * 256];
            ay += s * vc[m * 256 + 1];
        }
        size_t mr = (size_t)b * NN + n;
        size_t tile = mr >> 7; int rt = (int)(mr & 127);
        size_t e = (tile * 4 + (p >> 5)) * 8192 + (SWZ(rt * 128 + ((2 * p) & 63) * 2) >> 1);
        __nv_bfloat162 h2, l2;
        split2(ax, ay, h2, l2);
        *reinterpret_cast<__nv_bfloat162*>(CXh + e) = h2;
        *reinterpret_cast<__nv_bfloat162*>(CXl + e) = l2;
    }
}

// ---------------------------------------------------------------------------
extern "C" void kernel_launch(void* const* d_in, const int* in_sizes, int n_in,
                              void* d_out, int out_size) {
    const float* x   = (const float*)d_in[0];
    const float* mw1 = (const float*)d_in[1];
    const float* mb1 = (const float*)d_in[2];
    const float* mw2 = (const float*)d_in[3];
    const float* mb2 = (const float*)d_in[4];
    const float* mw3 = (const float*)d_in[5];
    const float* mb3 = (const float*)d_in[6];
    const float* qw  = (const float*)d_in[7];
    const float* qb  = (const float*)d_in[8];
    const float* kw  = (const float*)d_in[9];
    const float* kb  = (const float*)d_in[10];
    const float* vw  = (const float*)d_in[11];
    const float* vb  = (const float*)d_in[12];
    const float* inw = (const float*)d_in[13];
    const float* inb = (const float*)d_in[14];
    const float* ow  = (const float*)d_in[15];
    const float* ob  = (const float*)d_in[16];
    const float* ow1 = (const float*)d_in[17];
    const float* ob1 = (const float*)d_in[18];
    const float* ow2 = (const float*)d_in[19];
    const float* ob2 = (const float*)d_in[20];
    const float* ow3 = (const float*)d_in[21];
    const float* ob3 = (const float*)d_in[22];
    float* out = (float*)d_out;
    const float s = 0.17677669529663687f;

    char *R0, *R1, *R2, *R3, *RS;
    cudaGetSymbolAddress((void**)&R0, g_R0);
    cudaGetSymbolAddress((void**)&R1, g_R1);
    cudaGetSymbolAddress((void**)&R2, g_R2);
    cudaGetSymbolAddress((void**)&R3, g_R3);
    cudaGetSymbolAddress((void**)&RS, g_RS);

    typedef __nv_bfloat16 bf;
    const size_t E64 = (size_t)MTOT * 64, E256 = (size_t)MTOT * 256;
    bf *XAh = (bf*)R0, *XAl = XAh + E64;
    bf *S2h = (bf*)R1, *S2l = S2h + E256;
    bf *Gh  = (bf*)R2, *Gl  = Gh + E256;
    bf *Tqh = (bf*)R3, *Tql = Tqh + E256;
    bf *Tkh = (bf*)R0, *Tkl = Tkh + E256;
    bf *Tvh = (bf*)R1, *Tvl = Tvh + E256;
    float *QH = (float*)R2;
    float *KH = (float*)R3;
    float *VH = (float*)R0;
    bf *CXh = (bf*)R1, *CXl = CXh + E256;
    bf *PLh = (bf*)(RS + RS_PLH), *PLl = (bf*)(RS + RS_PLL);
    bf *H1h = (bf*)(RS + RS_H1H), *H1l = (bf*)(RS + RS_H1L);
    float *PLF = (float*)(RS + RS_PLF);
    float *scr = (float*)R3;   // fold scratch (prep-time only; dead before FQ)

    // ---- prep ----
    fold_k<<<dim3(256, 3), 256>>>(qw, kw, vw, mw3, scr);
    fold_b<<<3, 256>>>(qw, kw, vw, qb, kb, vb, mb3);
    PrepAll pa;
    const float* srcs[9] = {mw1, mw2, scr, inw, inw + 65536, inw + 131072,
                            ow, ow1, ow2};
    int Os[9]   = {128, 256, 768, 256, 256, 256, 256, 128, 64};
    int Ks[9]   = {7, 128, 256, 256, 256, 256, 256, 256, 128};
    int nchs[9] = {1, 2, 4, 4, 4, 4, 4, 4, 2};
    float scs[9] = {1.f, 1.f, 1.f, s, 1.f, 1.f, 1.f, 1.f, 1.f};
    int offs[9] = {W1OFF, W2OFF, FQOFF, WQOFF, WKOFF, WVOFF, OWOFF, O1OFF, O2OFF};
    for (int i = 0; i < 9; i++) {
        pa.src[i] = srcs[i]; pa.O[i] = Os[i]; pa.K[i] = Ks[i];
        pa.nch[i] = nchs[i]; pa.scale[i] = scs[i]; pa.off[i] = offs[i];
    }
    prep_w_all<<<dim3(64, 9), 256>>>(pa);
    prep_bias<<<1, 256>>>(mb1, mb2, inb, ob, ob1, ob2, ow3, ob3);
    prep_x<<<512, 256>>>(x, XAh, XAl);
    init_pool<<<256, 256>>>(PLF);

    cudaFuncSetAttribute(gemm_hmma,
                         cudaFuncAttributeMaxDynamicSharedMemorySize, GSMEM);
    cudaFuncSetAttribute(gemm12_k,
                         cudaFuncAttributeMaxDynamicSharedMemorySize, F_SMEM);
    cudaFuncSetAttribute(att_k, cudaFuncAttributeMaxDynamicSharedMemorySize,
                         ATT_FLOATS * 4);

    const int MT = MTOT / 128;  // 2944
    dim3 GF(2, MT), G256(4, MT), G768(12, MT),
         GH1(2, BSZ / 128), GH2(1, BSZ / 128);
    bf* Z = nullptr;
    float* F0 = nullptr;

    gemm12_k<<<GF, NT, F_SMEM>>>(XAh, XAl, S2h, S2l);
    agg2_k<<<BSZ, 128>>>(S2h, S2l, Gh, Gl);
    gemm_hmma<<<G768, NT, GSMEM>>>(Gh, Gl, Z, Z, Z, Z, 4, FQOFF, 0, 768,
                                   FQB, 1, 0, Tqh, Tql, Tkh, Tkl, Tvh, Tvl,
                                   F0, F0, F0);
    gemm_hmma<<<G256, NT, GSMEM>>>(Tqh, Tql, Z, Z, Z, Z, 4, WQOFF, 0, 256,
                                   BQO, 0, 1, Z, Z, Z, Z, Z, Z, QH, F0, F0);
    gemm_hmma<<<G256, NT, GSMEM>>>(Tkh, Tkl, Z, Z, Z, Z, 4, WKOFF, 0, 256,
                                   BKO, 0, 1, Z, Z, Z, Z, Z, Z, KH, F0, F0);
    gemm_hmma<<<G256, NT, GSMEM>>>(Tvh, Tvl, Z, Z, Z, Z, 4, WVOFF, 0, 256,
                                   BVO, 0, 1, Z, Z, Z, Z, Z, Z, VH, F0, F0);
    att_k<<<BSZ, NT, ATT_FLOATS * 4>>>(QH, KH, VH, CXh, CXl);
    gemm_hmma<<<G256, NT, GSMEM>>>(CXh, CXl, Z, Z, Z, Z, 4, OWOFF, 0, 256,
                                   OBO, 0, 2, Z, Z, Z, Z, Z, Z, PLF, F0, F0);
    pool2pair<<<BSZ, 128>>>(PLF, PLh, PLl);
    gemm_hmma<<<GH1, NT, GSMEM>>>(PLh, PLl, Z, Z, Z, Z, 4, O1OFF, 0, 128,
                                  OB1O, 1, 0, H1h, H1l, Z, Z, Z, Z, F0, F0, F0);
    gemm_hmma<<<GH2, NT, GSMEM>>>(H1h, H1l, Z, Z, Z, Z, 2, O2OFF, 0, 64,
                                  OB2O, 1, 3, Z, Z, Z, Z, Z, Z, out, F0, F0);
}